// round 2
// baseline (speedup 1.0000x reference)
#include <cuda_runtime.h>
#include <math.h>

#define NB 8
#define C1 128
#define HH 128
#define WW 128
#define HW (HH*WW)
#define KK 7
#define SS 4
#define DD 49
#define PD 52
#define NPH 31              // full unfold patch grid (31x31)
#define PP 19               // only virtual patches with ph',pw'<=18 reach the cropped output
#define NPATCH (PP*PP)

// ---------------- scratch (static device globals; no allocations) ----------------
__device__ float g_exsum[NB*C1*HW];       // exemplar_att*mask + exemplar
__device__ float g_qsum [NB*C1*HW];       // query_att*mask + query
__device__ float g_dwex [NB*C1*HW];       // dw(ex) after bn+relu
__device__ float g_dwq  [NB*C1*HW];       // dw(q)  after bn+relu
__device__ float g_cat  [NB*2*C1*HW];     // concat(exemplar_out, query_out)
__device__ float g_dwf  [NB*2*C1*HW];     // dwf(cat) after bn+relu

// smem layout (floats) for attention kernel
#define S_W    0
#define S_EX   (S_W   + C1*C1)
#define S_Q    (S_EX  + C1*PD)
#define S_COR  (S_Q   + C1*PD)
#define S_ATT  (S_COR + C1*PD)
#define S_A    (S_ATT + C1*PD)
#define S_A1   (S_A   + PD*PD)
#define S_B2   (S_A1  + PD*PD)
#define S_ME   (S_B2  + PD*PD)
#define S_MQ   (S_ME  + PD)
#define S_G1   (S_MQ  + PD)
#define S_G2   (S_G1  + C1)
#define S_TOT  (S_G2  + C1)
#define SMEM_BYTES (S_TOT * 4)

// =====================================================================
// Fused attention kernel: one CTA per (n, virtual patch b).
//
// KEY SEMANTICS (matches the reference's reshape, which scrambles axes):
//   within batch n, flat index m = true_c*961 + true_p; the attention view
//   has b = m // 128 (virtual patch), c' = m % 128 (virtual channel).
//   Recon places F[b, c', d] at image[c', (b//31)*7 + kh, (b%31)*7 + kw].
// =====================================================================
__global__ __launch_bounds__(512) void attn_kernel(
    const float* __restrict__ ex, const float* __restrict__ q,
    const float* __restrict__ wce, const float* __restrict__ g1,
    const float* __restrict__ g2)
{
    extern __shared__ float sm[];
    float* s_w   = sm + S_W;
    float* s_ex  = sm + S_EX;
    float* s_q   = sm + S_Q;
    float* s_cor = sm + S_COR;   // ex_corr, later reused for query_att
    float* s_att = sm + S_ATT;   // exemplar_att
    float* s_A   = sm + S_A;
    float* s_A1  = sm + S_A1;
    float* s_B2  = sm + S_B2;
    float* s_me  = sm + S_ME;
    float* s_mq  = sm + S_MQ;
    float* s_g1  = sm + S_G1;
    float* s_g2  = sm + S_G2;

    const int tid = threadIdx.x;
    const int n   = blockIdx.x / NPATCH;
    const int pv  = blockIdx.x % NPATCH;
    const int phv = pv / PP, pwv = pv % PP;   // virtual patch coords (output side)
    const int b   = phv * NPH + pwv;          // virtual patch index in [0, 961)

    // ---- load weights ----
    for (int i = tid; i < C1*C1; i += 512) s_w[i] = wce[i];
    if (tid < C1) { s_g1[tid] = g1[tid]; s_g2[tid] = g2[tid]; }
    // zero pad columns (d = 49..51) so 4-wide tiles are safe
    for (int i = tid; i < C1*3; i += 512) {
        int c = i/3, j = i%3;
        s_ex[c*PD + DD + j] = 0.f;
        s_q [c*PD + DD + j] = 0.f;
    }
    // ---- load scrambled patch rows ----
    const float* exn = ex + (size_t)n*C1*HW;
    const float* qn  = q  + (size_t)n*C1*HW;
    for (int i = tid; i < C1*DD; i += 512) {
        int cp = i / DD, d = i % DD;          // cp = virtual channel c'
        int m  = b*C1 + cp;                   // scrambled flat index
        int c  = m / 961;                     // true channel
        int p  = m % 961;                     // true patch
        int pht = p / NPH, pwt = p % NPH;     // true (input) patch coords
        int kh = d / KK, kw = d % KK;
        int gi = c*HW + (pht*SS + kh)*WW + (pwt*SS + kw);
        s_ex[cp*PD + d] = exn[gi];
        s_q [cp*PD + d] = qn [gi];
    }
    __syncthreads();

    // ---- ex_corr[c'][d] = sum_cc w[c'][cc] * ex[cc][d]  (4-wide on d) ----
    for (int t = tid; t < C1*13; t += 512) {
        int c = t / 13, dt = (t % 13) * 4;
        float a0=0.f, a1=0.f, a2=0.f, a3=0.f;
        const float* wr = s_w + c*C1;
        #pragma unroll 4
        for (int cc = 0; cc < C1; cc++) {
            float wv = wr[cc];
            const float* er = s_ex + cc*PD + dt;
            a0 += wv*er[0]; a1 += wv*er[1]; a2 += wv*er[2]; a3 += wv*er[3];
        }
        float* o = s_cor + c*PD + dt;
        o[0]=a0; o[1]=a1; o[2]=a2; o[3]=a3;
    }
    __syncthreads();

    // ---- A[d][e] = sum_c corr[c][d] * q[c][e] ----
    for (int t = tid; t < DD*DD; t += 512) {
        int d = t / DD, e = t % DD;
        float a = 0.f;
        #pragma unroll 4
        for (int c = 0; c < C1; c++) a += s_cor[c*PD + d] * s_q[c*PD + e];
        s_A[d*PD + e] = a;
    }
    __syncthreads();

    // ---- softmaxes: A1 over d (per column e), B2 over e (per row d) ----
    if (tid < DD) {                       // column softmax -> s_A1
        int e = tid;
        float m = -1e30f;
        for (int d = 0; d < DD; d++) m = fmaxf(m, s_A[d*PD + e]);
        float s = 0.f;
        for (int d = 0; d < DD; d++) { float v = expf(s_A[d*PD + e] - m); s_A1[d*PD + e] = v; s += v; }
        float r = 1.f / s;
        for (int d = 0; d < DD; d++) s_A1[d*PD + e] *= r;
    } else if (tid >= 64 && tid < 64 + DD) { // row softmax -> s_B2
        int d = tid - 64;
        float m = -1e30f;
        for (int e = 0; e < DD; e++) m = fmaxf(m, s_A[d*PD + e]);
        float s = 0.f;
        for (int e = 0; e < DD; e++) { float v = expf(s_A[d*PD + e] - m); s_B2[d*PD + e] = v; s += v; }
        float r = 1.f / s;
        for (int e = 0; e < DD; e++) s_B2[d*PD + e] *= r;
    }
    __syncthreads();

    // ---- query_att[c][e] = sum_d ex[c][d]*A1[d][e]   (into s_cor)
    //      exemplar_att[c][d] = sum_e q[c][e]*B2[d][e] (into s_att) ----
    for (int t = tid; t < C1*13; t += 512) {
        int c = t / 13, et = (t % 13) * 4;
        float a0=0.f, a1=0.f, a2=0.f, a3=0.f;
        for (int d = 0; d < DD; d++) {
            float ev = s_ex[c*PD + d];
            const float* ar = s_A1 + d*PD + et;
            a0 += ev*ar[0]; a1 += ev*ar[1]; a2 += ev*ar[2]; a3 += ev*ar[3];
        }
        float* o = s_cor + c*PD + et;
        o[0]=a0; o[1]=a1; o[2]=a2; o[3]=a3;
    }
    for (int t = tid; t < C1*13; t += 512) {
        int c = t / 13, dt = (t % 13) * 4;
        float a0=0.f, a1=0.f, a2=0.f, a3=0.f;
        for (int e = 0; e < DD; e++) {
            float qv = s_q[c*PD + e];
            a0 += qv * s_B2[(dt+0)*PD + e];
            a1 += qv * s_B2[(dt+1)*PD + e];
            a2 += qv * s_B2[(dt+2)*PD + e];
            a3 += qv * s_B2[(dt+3)*PD + e];
        }
        float* o = s_att + c*PD + dt;
        o[0]=a0; o[1]=a1; o[2]=a2; o[3]=a3;
    }
    __syncthreads();

    // ---- sigmoid gates (per output pixel == per (b,d)) ----
    if (tid < DD) {
        int d = tid; float s = 0.f;
        for (int c = 0; c < C1; c++) s += s_g1[c] * s_att[c*PD + d];
        s_me[d] = 1.f / (1.f + expf(-s));
    } else if (tid >= 64 && tid < 64 + DD) {
        int e = tid - 64; float s = 0.f;
        for (int c = 0; c < C1; c++) s += s_g2[c] * s_cor[c*PD + e];
        s_mq[e] = 1.f / (1.f + expf(-s));
    }
    __syncthreads();

    // ---- recon (output stride K=7, crop) + residual add, direct scatter.
    //      Output channel is the VIRTUAL channel c'. ----
    for (int i = tid; i < C1*DD; i += 512) {
        int c = i / DD, d = i % DD;
        int kh = d / KK, kw = d % KK;
        int y = phv*KK + kh, x = pwv*KK + kw;
        if (y < HH && x < WW) {
            size_t gi = (size_t)(n*C1 + c)*HW + y*WW + x;
            g_exsum[gi] = s_att[c*PD + d]*s_me[d] + ex[gi];
            g_qsum [gi] = s_cor[c*PD + d]*s_mq[d] + q [gi];
        }
    }
}

// =====================================================================
// Depthwise 3x3 (pad 1) + BN + ReLU
// =====================================================================
__global__ __launch_bounds__(256) void dw_kernel(
    const float* __restrict__ in, float* __restrict__ out,
    const float* __restrict__ w, const float* __restrict__ g,
    const float* __restrict__ b, int Ctot, int total)
{
    int idx = blockIdx.x*blockDim.x + threadIdx.x;
    if (idx >= total) return;
    int x = idx % WW;
    int y = (idx / WW) % HH;
    int c = (idx / HW) % Ctot;
    const float* ip = in + (size_t)(idx - (y*WW + x));  // (n,c) plane base
    const float* wc = w + c*9;
    float acc = 0.f;
    #pragma unroll
    for (int dy = -1; dy <= 1; dy++) {
        int yy = y + dy;
        if (yy < 0 || yy >= HH) continue;
        #pragma unroll
        for (int dx = -1; dx <= 1; dx++) {
            int xx = x + dx;
            if (xx < 0 || xx >= WW) continue;
            acc += wc[(dy+1)*3 + (dx+1)] * ip[yy*WW + xx];
        }
    }
    float gs = g[c] * rsqrtf(1.f + 1e-5f);
    float v = acc*gs + b[c];
    out[idx] = v > 0.f ? v : 0.f;
}

// =====================================================================
// Pointwise 1x1 conv as SGEMM (Cout=128) + BN + ReLU.
// =====================================================================
template<int CIN>
__global__ __launch_bounds__(256) void pw_kernel(
    const float* __restrict__ in, float* __restrict__ out,
    const float* __restrict__ w, const float* __restrict__ gsc,
    const float* __restrict__ bsc, int ostride, int co_off)
{
    __shared__ float As[16][64];
    __shared__ float Bs[16][64];
    const int n   = blockIdx.z;
    const int px0 = blockIdx.x * 64;
    const int co0 = blockIdx.y * 64;
    const int t   = threadIdx.x;
    const int tx  = t % 16, ty = t / 16;

    float acc[4][4] = {};
    const float* inb = in + (size_t)n*CIN*HW + px0;

    for (int kt = 0; kt < CIN; kt += 16) {
        {   // B tile: 16 k-rows x 64 px (coalesced float4)
            int kr = t / 16;
            int pc = (t % 16) * 4;
            float4 v = *reinterpret_cast<const float4*>(inb + (size_t)(kt + kr)*HW + pc);
            *reinterpret_cast<float4*>(&Bs[kr][pc]) = v;
        }
        {   // A tile: 64 co x 16 k, stored transposed
            int ci = t / 4;
            int k4 = (t % 4) * 4;
            float4 v = *reinterpret_cast<const float4*>(w + (size_t)(co0 + ci)*CIN + kt + k4);
            As[k4+0][ci] = v.x; As[k4+1][ci] = v.y; As[k4+2][ci] = v.z; As[k4+3][ci] = v.w;
        }
        __syncthreads();
        #pragma unroll
        for (int k = 0; k < 16; k++) {
            float4 a  = *reinterpret_cast<float4*>(&As[k][ty*4]);
            float4 bv = *reinterpret_cast<float4*>(&Bs[k][tx*4]);
            acc[0][0] += a.x*bv.x; acc[0][1] += a.x*bv.y; acc[0][2] += a.x*bv.z; acc[0][3] += a.x*bv.w;
            acc[1][0] += a.y*bv.x; acc[1][1] += a.y*bv.y; acc[1][2] += a.y*bv.z; acc[1][3] += a.y*bv.w;
            acc[2][0] += a.z*bv.x; acc[2][1] += a.z*bv.y; acc[2][2] += a.z*bv.z; acc[2][3] += a.z*bv.w;
            acc[3][0] += a.w*bv.x; acc[3][1] += a.w*bv.y; acc[3][2] += a.w*bv.z; acc[3][3] += a.w*bv.w;
        }
        __syncthreads();
    }

    #pragma unroll
    for (int i = 0; i < 4; i++) {
        int co = co0 + ty*4 + i;
        float gv = gsc[co] * rsqrtf(1.f + 1e-5f);
        float bb = bsc[co];
        float4 o;
        o.x = fmaxf(acc[i][0]*gv + bb, 0.f);
        o.y = fmaxf(acc[i][1]*gv + bb, 0.f);
        o.z = fmaxf(acc[i][2]*gv + bb, 0.f);
        o.w = fmaxf(acc[i][3]*gv + bb, 0.f);
        *reinterpret_cast<float4*>(out + ((size_t)n*ostride + co_off + co)*HW + px0 + tx*4) = o;
    }
}

// =====================================================================
extern "C" void kernel_launch(void* const* d_in, const int* in_sizes, int n_in,
                              void* d_out, int out_size)
{
    const float* exemplar = (const float*)d_in[0];
    const float* query    = (const float*)d_in[1];
    const float* w_conv_e = (const float*)d_in[2];
    const float* w_gate1  = (const float*)d_in[3];
    const float* w_gate2  = (const float*)d_in[4];
    const float* dw1_w    = (const float*)d_in[5];
    const float* bn1a_g   = (const float*)d_in[6];
    const float* bn1a_b   = (const float*)d_in[7];
    const float* pw1_w    = (const float*)d_in[8];
    const float* bn1b_g   = (const float*)d_in[9];
    const float* bn1b_b   = (const float*)d_in[10];
    const float* dwf_w    = (const float*)d_in[11];
    const float* bnfa_g   = (const float*)d_in[12];
    const float* bnfa_b   = (const float*)d_in[13];
    const float* pwf_w    = (const float*)d_in[14];
    const float* bnfb_g   = (const float*)d_in[15];
    const float* bnfb_b   = (const float*)d_in[16];

    float *p_exsum, *p_qsum, *p_dwex, *p_dwq, *p_cat, *p_dwf;
    cudaGetSymbolAddress((void**)&p_exsum, g_exsum);
    cudaGetSymbolAddress((void**)&p_qsum,  g_qsum);
    cudaGetSymbolAddress((void**)&p_dwex,  g_dwex);
    cudaGetSymbolAddress((void**)&p_dwq,   g_dwq);
    cudaGetSymbolAddress((void**)&p_cat,   g_cat);
    cudaGetSymbolAddress((void**)&p_dwf,   g_dwf);

    cudaFuncSetAttribute(attn_kernel, cudaFuncAttributeMaxDynamicSharedMemorySize, SMEM_BYTES);

    // 1) fused attention + gates + residual add (only the 19x19 used virtual patches)
    attn_kernel<<<NB*NPATCH, 512, SMEM_BYTES>>>(exemplar, query, w_conv_e, w_gate1, w_gate2);

    // 2) dsconv stage 1 on both streams (shared weights)
    int tot1 = NB*C1*HW;
    dw_kernel<<<tot1/256, 256>>>(p_exsum, p_dwex, dw1_w, bn1a_g, bn1a_b, C1, tot1);
    dw_kernel<<<tot1/256, 256>>>(p_qsum,  p_dwq,  dw1_w, bn1a_g, bn1a_b, C1, tot1);
    pw_kernel<C1><<<dim3(HW/64, 2, NB), 256>>>(p_dwex, p_cat, pw1_w, bn1b_g, bn1b_b, 2*C1, 0);
    pw_kernel<C1><<<dim3(HW/64, 2, NB), 256>>>(p_dwq,  p_cat, pw1_w, bn1b_g, bn1b_b, 2*C1, C1);

    // 3) final dsconv on the (implicit) concat
    int tot2 = NB*2*C1*HW;
    dw_kernel<<<tot2/256, 256>>>(p_cat, p_dwf, dwf_w, bnfa_g, bnfa_b, 2*C1, tot2);
    pw_kernel<2*C1><<<dim3(HW/64, 2, NB), 256>>>(p_dwf, (float*)d_out, pwf_w, bnfb_g, bnfb_b, C1, 0);
}

// round 3
// speedup vs baseline: 1.6510x; 1.6510x over previous
#include <cuda_runtime.h>
#include <math.h>

#define NB 8
#define C1 128
#define HH 128
#define WW 128
#define HW (HH*WW)
#define KK 7
#define SS 4
#define DD 49
#define PD 52
#define NPH 31
#define PP 19
#define NPATCH (PP*PP)

// ---------------- scratch (static device globals) ----------------
__device__ float g_exsum[NB*C1*HW];
__device__ float g_qsum [NB*C1*HW];
__device__ float g_dwex [NB*C1*HW];
__device__ float g_dwq  [NB*C1*HW];
__device__ float g_cat  [NB*2*C1*HW];
__device__ float g_dwf  [NB*2*C1*HW];

// smem layout (floats)
#define S_W    0
#define S_EX   (S_W   + C1*C1)
#define S_Q    (S_EX  + C1*PD)
#define S_COR  (S_Q   + C1*PD)
#define S_ATT  (S_COR + C1*PD)
#define S_A    (S_ATT + C1*PD)
#define S_A2   (S_A   + PD*PD)
#define S_A1   (S_A2  + PD*PD)
#define S_B2   (S_A1  + PD*PD)   // stored TRANSPOSED: s_B2[e*PD + d]
#define S_ME   (S_B2  + PD*PD)
#define S_MQ   (S_ME  + PD)
#define S_G1   (S_MQ  + PD)
#define S_G2   (S_G1  + C1)
#define S_TOT  (S_G2  + C1)
#define SMEM_BYTES (S_TOT * 4)   // 216,736 B

// =====================================================================
// Fused attention kernel: one CTA per (n, virtual patch b).
// Scrambled-axes semantics: m = true_c*961 + true_p;
// b = m/128 (virtual patch), c' = m%128 (virtual channel).
// =====================================================================
__global__ __launch_bounds__(512) void attn_kernel(
    const float* __restrict__ ex, const float* __restrict__ q,
    const float* __restrict__ wce, const float* __restrict__ g1,
    const float* __restrict__ g2)
{
    extern __shared__ float sm[];
    float* s_w   = sm + S_W;
    float* s_ex  = sm + S_EX;
    float* s_q   = sm + S_Q;
    float* s_cor = sm + S_COR;   // ex_corr, later reused for query_att
    float* s_att = sm + S_ATT;   // exemplar_att
    float* s_A   = sm + S_A;
    float* s_A2  = sm + S_A2;    // split-K partial
    float* s_A1  = sm + S_A1;
    float* s_B2  = sm + S_B2;    // transposed [e][d]
    float* s_me  = sm + S_ME;
    float* s_mq  = sm + S_MQ;
    float* s_g1  = sm + S_G1;
    float* s_g2  = sm + S_G2;

    const int tid  = threadIdx.x;
    const int lane = tid & 31;
    const int wid  = tid >> 5;
    const int n    = blockIdx.x / NPATCH;
    const int pv   = blockIdx.x % NPATCH;
    const int phv  = pv / PP, pwv = pv % PP;
    const int b    = phv * NPH + pwv;

    // ---- load weights ----
    for (int i = tid; i < C1*C1; i += 512) s_w[i] = wce[i];
    if (tid < C1) { s_g1[tid] = g1[tid]; s_g2[tid] = g2[tid]; }
    for (int i = tid; i < C1*3; i += 512) {
        int c = i/3, j = i%3;
        s_ex[c*PD + DD + j] = 0.f;
        s_q [c*PD + DD + j] = 0.f;
    }
    // ---- load scrambled patch rows ----
    const float* exn = ex + (size_t)n*C1*HW;
    const float* qn  = q  + (size_t)n*C1*HW;
    for (int i = tid; i < C1*DD; i += 512) {
        int cp = i / DD, d = i % DD;
        int m  = b*C1 + cp;
        int c  = m / 961;
        int p  = m % 961;
        int pht = p / NPH, pwt = p % NPH;
        int kh = d / KK, kw = d % KK;
        int gi = c*HW + (pht*SS + kh)*WW + (pwt*SS + kw);
        s_ex[cp*PD + d] = exn[gi];
        s_q [cp*PD + d] = qn [gi];
    }
    __syncthreads();

    // ---- stage 1: corr[c][d] = sum_k w[c][k] * ex[k][d]  (4c x 4d tiles) ----
    if (tid < 416) {
        const int c0 = (tid / 13) * 4;
        const int d0 = (tid % 13) * 4;
        float acc[4][4] = {};
        #pragma unroll 4
        for (int k = 0; k < C1; k++) {
            float4 ev = *(const float4*)&s_ex[k*PD + d0];
            float w0 = s_w[(c0+0)*C1 + k];
            float w1 = s_w[(c0+1)*C1 + k];
            float w2 = s_w[(c0+2)*C1 + k];
            float w3 = s_w[(c0+3)*C1 + k];
            acc[0][0]+=w0*ev.x; acc[0][1]+=w0*ev.y; acc[0][2]+=w0*ev.z; acc[0][3]+=w0*ev.w;
            acc[1][0]+=w1*ev.x; acc[1][1]+=w1*ev.y; acc[1][2]+=w1*ev.z; acc[1][3]+=w1*ev.w;
            acc[2][0]+=w2*ev.x; acc[2][1]+=w2*ev.y; acc[2][2]+=w2*ev.z; acc[2][3]+=w2*ev.w;
            acc[3][0]+=w3*ev.x; acc[3][1]+=w3*ev.y; acc[3][2]+=w3*ev.z; acc[3][3]+=w3*ev.w;
        }
        #pragma unroll
        for (int i = 0; i < 4; i++)
            *(float4*)&s_cor[(c0+i)*PD + d0] = make_float4(acc[i][0],acc[i][1],acc[i][2],acc[i][3]);
    }
    __syncthreads();

    // ---- stage 2: A[d][e] = sum_c corr[c][d]*q[c][e]  (4d x 4e, split-K x2) ----
    if (tid < 338) {
        const int t  = tid % 169;
        const int kh = tid / 169;
        const int d0 = (t / 13) * 4;
        const int e0 = (t % 13) * 4;
        const int k0 = kh * 64;
        float acc[4][4] = {};
        #pragma unroll 4
        for (int c = k0; c < k0 + 64; c++) {
            float4 cd = *(const float4*)&s_cor[c*PD + d0];
            float4 qe = *(const float4*)&s_q  [c*PD + e0];
            acc[0][0]+=cd.x*qe.x; acc[0][1]+=cd.x*qe.y; acc[0][2]+=cd.x*qe.z; acc[0][3]+=cd.x*qe.w;
            acc[1][0]+=cd.y*qe.x; acc[1][1]+=cd.y*qe.y; acc[1][2]+=cd.y*qe.z; acc[1][3]+=cd.y*qe.w;
            acc[2][0]+=cd.z*qe.x; acc[2][1]+=cd.z*qe.y; acc[2][2]+=cd.z*qe.z; acc[2][3]+=cd.z*qe.w;
            acc[3][0]+=cd.w*qe.x; acc[3][1]+=cd.w*qe.y; acc[3][2]+=cd.w*qe.z; acc[3][3]+=cd.w*qe.w;
        }
        float* dst = kh ? s_A2 : s_A;
        #pragma unroll
        for (int i = 0; i < 4; i++)
            *(float4*)&dst[(d0+i)*PD + e0] = make_float4(acc[i][0],acc[i][1],acc[i][2],acc[i][3]);
    }
    __syncthreads();

    // ---- softmaxes (warp per row/col; A = s_A + s_A2) ----
    for (int task = wid; task < 98; task += 16) {
        if (task < 49) {            // column softmax over d -> s_A1[d][e]
            int e = task;
            float v0 = s_A[lane*PD + e] + s_A2[lane*PD + e];
            float v1 = (lane < 17) ? s_A[(lane+32)*PD + e] + s_A2[(lane+32)*PD + e] : -1e30f;
            float m = fmaxf(v0, v1);
            #pragma unroll
            for (int o = 16; o; o >>= 1) m = fmaxf(m, __shfl_xor_sync(~0u, m, o));
            float p0 = __expf(v0 - m), p1 = (lane < 17) ? __expf(v1 - m) : 0.f;
            float s = p0 + p1;
            #pragma unroll
            for (int o = 16; o; o >>= 1) s += __shfl_xor_sync(~0u, s, o);
            float r = 1.f / s;
            s_A1[lane*PD + e] = p0 * r;
            if (lane < 17) s_A1[(lane+32)*PD + e] = p1 * r;
        } else {                    // row softmax over e -> s_B2[e][d] (transposed)
            int d = task - 49;
            float v0 = s_A[d*PD + lane] + s_A2[d*PD + lane];
            float v1 = (lane < 17) ? s_A[d*PD + lane+32] + s_A2[d*PD + lane+32] : -1e30f;
            float m = fmaxf(v0, v1);
            #pragma unroll
            for (int o = 16; o; o >>= 1) m = fmaxf(m, __shfl_xor_sync(~0u, m, o));
            float p0 = __expf(v0 - m), p1 = (lane < 17) ? __expf(v1 - m) : 0.f;
            float s = p0 + p1;
            #pragma unroll
            for (int o = 16; o; o >>= 1) s += __shfl_xor_sync(~0u, s, o);
            float r = 1.f / s;
            s_B2[lane*PD + d] = p0 * r;
            if (lane < 17) s_B2[(lane+32)*PD + d] = p1 * r;
        }
    }
    __syncthreads();

    // ---- stage 3a: query_att[c][e] = sum_d ex[c][d]*A1[d][e] (into s_cor) ----
    if (tid < 416) {
        const int c0 = (tid / 13) * 4;
        const int e0 = (tid % 13) * 4;
        float acc[4][4] = {};
        #pragma unroll 7
        for (int d = 0; d < DD; d++) {
            float4 av = *(const float4*)&s_A1[d*PD + e0];
            float x0 = s_ex[(c0+0)*PD + d];
            float x1 = s_ex[(c0+1)*PD + d];
            float x2 = s_ex[(c0+2)*PD + d];
            float x3 = s_ex[(c0+3)*PD + d];
            acc[0][0]+=x0*av.x; acc[0][1]+=x0*av.y; acc[0][2]+=x0*av.z; acc[0][3]+=x0*av.w;
            acc[1][0]+=x1*av.x; acc[1][1]+=x1*av.y; acc[1][2]+=x1*av.z; acc[1][3]+=x1*av.w;
            acc[2][0]+=x2*av.x; acc[2][1]+=x2*av.y; acc[2][2]+=x2*av.z; acc[2][3]+=x2*av.w;
            acc[3][0]+=x3*av.x; acc[3][1]+=x3*av.y; acc[3][2]+=x3*av.z; acc[3][3]+=x3*av.w;
        }
        #pragma unroll
        for (int i = 0; i < 4; i++)
            *(float4*)&s_cor[(c0+i)*PD + e0] = make_float4(acc[i][0],acc[i][1],acc[i][2],acc[i][3]);
    }
    __syncthreads();   // s_cor reuse: all stage-2 readers done long ago; keep order strict

    // ---- stage 3b: exemplar_att[c][d] = sum_e q[c][e]*B2t[e][d] (into s_att) ----
    if (tid < 416) {
        const int c0 = (tid / 13) * 4;
        const int d0 = (tid % 13) * 4;
        float acc[4][4] = {};
        #pragma unroll 7
        for (int e = 0; e < DD; e++) {
            float4 bv = *(const float4*)&s_B2[e*PD + d0];
            float x0 = s_q[(c0+0)*PD + e];
            float x1 = s_q[(c0+1)*PD + e];
            float x2 = s_q[(c0+2)*PD + e];
            float x3 = s_q[(c0+3)*PD + e];
            acc[0][0]+=x0*bv.x; acc[0][1]+=x0*bv.y; acc[0][2]+=x0*bv.z; acc[0][3]+=x0*bv.w;
            acc[1][0]+=x1*bv.x; acc[1][1]+=x1*bv.y; acc[1][2]+=x1*bv.z; acc[1][3]+=x1*bv.w;
            acc[2][0]+=x2*bv.x; acc[2][1]+=x2*bv.y; acc[2][2]+=x2*bv.z; acc[2][3]+=x2*bv.w;
            acc[3][0]+=x3*bv.x; acc[3][1]+=x3*bv.y; acc[3][2]+=x3*bv.z; acc[3][3]+=x3*bv.w;
        }
        #pragma unroll
        for (int i = 0; i < 4; i++)
            *(float4*)&s_att[(c0+i)*PD + d0] = make_float4(acc[i][0],acc[i][1],acc[i][2],acc[i][3]);
    }
    __syncthreads();

    // ---- gates: warp per output pixel ----
    for (int task = wid; task < 98; task += 16) {
        if (task < 49) {
            int d = task; float s = 0.f;
            #pragma unroll
            for (int j = 0; j < 4; j++) { int c = lane + 32*j; s += s_g1[c] * s_att[c*PD + d]; }
            #pragma unroll
            for (int o = 16; o; o >>= 1) s += __shfl_xor_sync(~0u, s, o);
            if (lane == 0) s_me[d] = 1.f / (1.f + __expf(-s));
        } else {
            int e = task - 49; float s = 0.f;
            #pragma unroll
            for (int j = 0; j < 4; j++) { int c = lane + 32*j; s += s_g2[c] * s_cor[c*PD + e]; }
            #pragma unroll
            for (int o = 16; o; o >>= 1) s += __shfl_xor_sync(~0u, s, o);
            if (lane == 0) s_mq[e] = 1.f / (1.f + __expf(-s));
        }
    }
    __syncthreads();

    // ---- recon + residual, direct scatter ----
    for (int i = tid; i < C1*DD; i += 512) {
        int c = i / DD, d = i % DD;
        int kh = d / KK, kw = d % KK;
        int y = phv*KK + kh, x = pwv*KK + kw;
        if (y < HH && x < WW) {
            size_t gi = (size_t)(n*C1 + c)*HW + y*WW + x;
            g_exsum[gi] = s_att[c*PD + d]*s_me[d] + ex[gi];
            g_qsum [gi] = s_cor[c*PD + d]*s_mq[d] + q [gi];
        }
    }
}

// =====================================================================
// Depthwise 3x3 (pad 1) + BN + ReLU
// =====================================================================
__global__ __launch_bounds__(256) void dw_kernel(
    const float* __restrict__ in, float* __restrict__ out,
    const float* __restrict__ w, const float* __restrict__ g,
    const float* __restrict__ b, int Ctot, int total)
{
    int idx = blockIdx.x*blockDim.x + threadIdx.x;
    if (idx >= total) return;
    int x = idx % WW;
    int y = (idx / WW) % HH;
    int c = (idx / HW) % Ctot;
    const float* ip = in + (size_t)(idx - (y*WW + x));
    const float* wc = w + c*9;
    float acc = 0.f;
    #pragma unroll
    for (int dy = -1; dy <= 1; dy++) {
        int yy = y + dy;
        if (yy < 0 || yy >= HH) continue;
        #pragma unroll
        for (int dx = -1; dx <= 1; dx++) {
            int xx = x + dx;
            if (xx < 0 || xx >= WW) continue;
            acc += wc[(dy+1)*3 + (dx+1)] * ip[yy*WW + xx];
        }
    }
    float gs = g[c] * rsqrtf(1.f + 1e-5f);
    float v = acc*gs + b[c];
    out[idx] = v > 0.f ? v : 0.f;
}

// =====================================================================
// Pointwise 1x1 conv as SGEMM: 128co x 128px tile, 8x8 micro (split 64+64).
// =====================================================================
template<int CIN>
__global__ __launch_bounds__(256) void pw_kernel(
    const float* __restrict__ in, float* __restrict__ out,
    const float* __restrict__ w, const float* __restrict__ gsc,
    const float* __restrict__ bsc, int ostride, int co_off)
{
    __shared__ float As[8][128];
    __shared__ float Bs[8][128];
    const int n   = blockIdx.z;
    const int px0 = blockIdx.x * 128;
    const int t   = threadIdx.x;
    const int tx  = t % 16, ty = t / 16;
    const int ci  = t % 128, k4 = (t / 128) * 4;
    const int kr  = t / 32,  pc = (t % 32) * 4;

    float acc[8][8] = {};
    const float* inb = in + (size_t)n*CIN*HW + px0;

    for (int kt = 0; kt < CIN; kt += 8) {
        float4 wv = *(const float4*)(w + (size_t)ci*CIN + kt + k4);
        As[k4+0][ci] = wv.x; As[k4+1][ci] = wv.y; As[k4+2][ci] = wv.z; As[k4+3][ci] = wv.w;
        *(float4*)&Bs[kr][pc] = *(const float4*)(inb + (size_t)(kt + kr)*HW + pc);
        __syncthreads();
        #pragma unroll
        for (int k = 0; k < 8; k++) {
            float4 a0 = *(float4*)&As[k][ty*4];
            float4 a1 = *(float4*)&As[k][64 + ty*4];
            float4 b0 = *(float4*)&Bs[k][tx*4];
            float4 b1 = *(float4*)&Bs[k][64 + tx*4];
            float av[8] = {a0.x,a0.y,a0.z,a0.w,a1.x,a1.y,a1.z,a1.w};
            float bv[8] = {b0.x,b0.y,b0.z,b0.w,b1.x,b1.y,b1.z,b1.w};
            #pragma unroll
            for (int i = 0; i < 8; i++)
                #pragma unroll
                for (int j = 0; j < 8; j++)
                    acc[i][j] += av[i] * bv[j];
        }
        __syncthreads();
    }

    #pragma unroll
    for (int i = 0; i < 8; i++) {
        int co = (i < 4) ? (ty*4 + i) : (64 + ty*4 + (i - 4));
        float gv = gsc[co] * rsqrtf(1.f + 1e-5f);
        float bb = bsc[co];
        float* ob = out + ((size_t)n*ostride + co_off + co)*HW + px0;
        float4 o0, o1;
        o0.x = fmaxf(acc[i][0]*gv + bb, 0.f);
        o0.y = fmaxf(acc[i][1]*gv + bb, 0.f);
        o0.z = fmaxf(acc[i][2]*gv + bb, 0.f);
        o0.w = fmaxf(acc[i][3]*gv + bb, 0.f);
        o1.x = fmaxf(acc[i][4]*gv + bb, 0.f);
        o1.y = fmaxf(acc[i][5]*gv + bb, 0.f);
        o1.z = fmaxf(acc[i][6]*gv + bb, 0.f);
        o1.w = fmaxf(acc[i][7]*gv + bb, 0.f);
        *(float4*)(ob + tx*4)      = o0;
        *(float4*)(ob + 64 + tx*4) = o1;
    }
}

// =====================================================================
extern "C" void kernel_launch(void* const* d_in, const int* in_sizes, int n_in,
                              void* d_out, int out_size)
{
    const float* exemplar = (const float*)d_in[0];
    const float* query    = (const float*)d_in[1];
    const float* w_conv_e = (const float*)d_in[2];
    const float* w_gate1  = (const float*)d_in[3];
    const float* w_gate2  = (const float*)d_in[4];
    const float* dw1_w    = (const float*)d_in[5];
    const float* bn1a_g   = (const float*)d_in[6];
    const float* bn1a_b   = (const float*)d_in[7];
    const float* pw1_w    = (const float*)d_in[8];
    const float* bn1b_g   = (const float*)d_in[9];
    const float* bn1b_b   = (const float*)d_in[10];
    const float* dwf_w    = (const float*)d_in[11];
    const float* bnfa_g   = (const float*)d_in[12];
    const float* bnfa_b   = (const float*)d_in[13];
    const float* pwf_w    = (const float*)d_in[14];
    const float* bnfb_g   = (const float*)d_in[15];
    const float* bnfb_b   = (const float*)d_in[16];

    float *p_exsum, *p_qsum, *p_dwex, *p_dwq, *p_cat, *p_dwf;
    cudaGetSymbolAddress((void**)&p_exsum, g_exsum);
    cudaGetSymbolAddress((void**)&p_qsum,  g_qsum);
    cudaGetSymbolAddress((void**)&p_dwex,  g_dwex);
    cudaGetSymbolAddress((void**)&p_dwq,   g_dwq);
    cudaGetSymbolAddress((void**)&p_cat,   g_cat);
    cudaGetSymbolAddress((void**)&p_dwf,   g_dwf);

    cudaFuncSetAttribute(attn_kernel, cudaFuncAttributeMaxDynamicSharedMemorySize, SMEM_BYTES);

    attn_kernel<<<NB*NPATCH, 512, SMEM_BYTES>>>(exemplar, query, w_conv_e, w_gate1, w_gate2);

    int tot1 = NB*C1*HW;
    dw_kernel<<<tot1/256, 256>>>(p_exsum, p_dwex, dw1_w, bn1a_g, bn1a_b, C1, tot1);
    dw_kernel<<<tot1/256, 256>>>(p_qsum,  p_dwq,  dw1_w, bn1a_g, bn1a_b, C1, tot1);
    pw_kernel<C1><<<dim3(HW/128, 1, NB), 256>>>(p_dwex, p_cat, pw1_w, bn1b_g, bn1b_b, 2*C1, 0);
    pw_kernel<C1><<<dim3(HW/128, 1, NB), 256>>>(p_dwq,  p_cat, pw1_w, bn1b_g, bn1b_b, 2*C1, C1);

    int tot2 = NB*2*C1*HW;
    dw_kernel<<<tot2/256, 256>>>(p_cat, p_dwf, dwf_w, bnfa_g, bnfa_b, 2*C1, tot2);
    pw_kernel<2*C1><<<dim3(HW/128, 1, NB), 256>>>(p_dwf, (float*)d_out, pwf_w, bnfb_g, bnfb_b, C1, 0);
}

// round 4
// speedup vs baseline: 1.8255x; 1.1057x over previous
#include <cuda_runtime.h>
#include <math.h>

#define NB 8
#define C1 128
#define HH 128
#define WW 128
#define HW (HH*WW)
#define KK 7
#define SS 4
#define DD 49
#define PD 52
#define NPH 31
#define PP 19
#define NPATCH (PP*PP)

// ---------------- scratch (static device globals) ----------------
__device__ float g_exsum[NB*C1*HW];
__device__ float g_qsum [NB*C1*HW];
__device__ float g_dwex [NB*C1*HW];
__device__ float g_dwq  [NB*C1*HW];
__device__ float g_cat  [NB*2*C1*HW];
__device__ float g_dwf  [NB*2*C1*HW];

// smem layout (floats) — 4 big regions + stats. Aliasing by lifetime:
//   S_EX:   ex patches          -> (3b) exemplar_att
//   S_Q:    q patches
//   S_COR:  ex_corr             -> (3a) query_att
//   S_ATTR: A @ +0, A2 @ +2704  -> pass2 in-place: B2 @ +0, A1 @ +2704
#define S_EX    0
#define S_Q     (C1*PD)          // 6656
#define S_COR   (2*C1*PD)
#define S_ATTR  (3*C1*PD)
#define A1_OFF  2704             // 52*52
#define S_CMAX  (4*C1*PD)
#define S_CRS   (S_CMAX + PD)
#define S_RMAX  (S_CRS  + PD)
#define S_RRS   (S_RMAX + PD)
#define S_ME    (S_RRS  + PD)
#define S_MQ    (S_ME   + PD)
#define S_G1    (S_MQ   + PD)
#define S_G2    (S_G1   + C1)
#define S_TOT   (S_G2   + C1)
#define SMEM_BYTES (S_TOT * 4)   // 108,768 B -> 2 CTAs/SM

// =====================================================================
// Fused attention kernel: one CTA per (n, virtual patch b).
// Scrambled-axes semantics: m = true_c*961 + true_p;
// b = m/128 (virtual patch), c' = m%128 (virtual channel).
// =====================================================================
__global__ __launch_bounds__(512, 2) void attn_kernel(
    const float* __restrict__ ex, const float* __restrict__ q,
    const float* __restrict__ wce, const float* __restrict__ g1,
    const float* __restrict__ g2)
{
    extern __shared__ float sm[];
    float* s_ex  = sm + S_EX;
    float* s_q   = sm + S_Q;
    float* s_cor = sm + S_COR;
    float* s_a0  = sm + S_ATTR;          // A, then B2 (in place)
    float* s_a1  = sm + S_ATTR + A1_OFF; // A2, then A1 (in place)
    float* s_cmax= sm + S_CMAX;
    float* s_crs = sm + S_CRS;
    float* s_rmax= sm + S_RMAX;
    float* s_rrs = sm + S_RRS;
    float* s_me  = sm + S_ME;
    float* s_mq  = sm + S_MQ;
    float* s_g1  = sm + S_G1;
    float* s_g2  = sm + S_G2;

    const int tid  = threadIdx.x;
    const int lane = tid & 31;
    const int wid  = tid >> 5;
    const int n    = blockIdx.x / NPATCH;
    const int pv   = blockIdx.x % NPATCH;
    const int phv  = pv / PP, pwv = pv % PP;
    const int b    = phv * NPH + pwv;

    if (tid < C1) { s_g1[tid] = g1[tid]; s_g2[tid] = g2[tid]; }
    for (int i = tid; i < C1*3; i += 512) {
        int c = i/3, j = i%3;
        s_ex[c*PD + DD + j] = 0.f;
        s_q [c*PD + DD + j] = 0.f;
    }
    const float* exn = ex + (size_t)n*C1*HW;
    const float* qn  = q  + (size_t)n*C1*HW;
    for (int i = tid; i < C1*DD; i += 512) {
        int cp = i / DD, d = i % DD;
        int m  = b*C1 + cp;
        int c  = m / 961;
        int p  = m % 961;
        int pht = p / NPH, pwt = p % NPH;
        int kh = d / KK, kw = d % KK;
        int gi = c*HW + (pht*SS + kh)*WW + (pwt*SS + kw);
        s_ex[cp*PD + d] = exn[gi];
        s_q [cp*PD + d] = qn [gi];
    }
    __syncthreads();

    // ---- stage 1: corr[c][d] = sum_k w[c][k]*ex[k][d]; w straight from gmem ----
    if (tid < 416) {
        const int c0 = (tid / 13) * 4;
        const int d0 = (tid % 13) * 4;
        float acc[4][4] = {};
        const float* w0 = wce + (size_t)(c0+0)*C1;
        const float* w1 = wce + (size_t)(c0+1)*C1;
        const float* w2 = wce + (size_t)(c0+2)*C1;
        const float* w3 = wce + (size_t)(c0+3)*C1;
        for (int k4 = 0; k4 < C1; k4 += 4) {
            float4 e0v = *(const float4*)&s_ex[(k4+0)*PD + d0];
            float4 e1v = *(const float4*)&s_ex[(k4+1)*PD + d0];
            float4 e2v = *(const float4*)&s_ex[(k4+2)*PD + d0];
            float4 e3v = *(const float4*)&s_ex[(k4+3)*PD + d0];
            {
                float4 wa = __ldg((const float4*)(w0 + k4));
                acc[0][0]+=wa.x*e0v.x+wa.y*e1v.x+wa.z*e2v.x+wa.w*e3v.x;
                acc[0][1]+=wa.x*e0v.y+wa.y*e1v.y+wa.z*e2v.y+wa.w*e3v.y;
                acc[0][2]+=wa.x*e0v.z+wa.y*e1v.z+wa.z*e2v.z+wa.w*e3v.z;
                acc[0][3]+=wa.x*e0v.w+wa.y*e1v.w+wa.z*e2v.w+wa.w*e3v.w;
            }
            {
                float4 wa = __ldg((const float4*)(w1 + k4));
                acc[1][0]+=wa.x*e0v.x+wa.y*e1v.x+wa.z*e2v.x+wa.w*e3v.x;
                acc[1][1]+=wa.x*e0v.y+wa.y*e1v.y+wa.z*e2v.y+wa.w*e3v.y;
                acc[1][2]+=wa.x*e0v.z+wa.y*e1v.z+wa.z*e2v.z+wa.w*e3v.z;
                acc[1][3]+=wa.x*e0v.w+wa.y*e1v.w+wa.z*e2v.w+wa.w*e3v.w;
            }
            {
                float4 wa = __ldg((const float4*)(w2 + k4));
                acc[2][0]+=wa.x*e0v.x+wa.y*e1v.x+wa.z*e2v.x+wa.w*e3v.x;
                acc[2][1]+=wa.x*e0v.y+wa.y*e1v.y+wa.z*e2v.y+wa.w*e3v.y;
                acc[2][2]+=wa.x*e0v.z+wa.y*e1v.z+wa.z*e2v.z+wa.w*e3v.z;
                acc[2][3]+=wa.x*e0v.w+wa.y*e1v.w+wa.z*e2v.w+wa.w*e3v.w;
            }
            {
                float4 wa = __ldg((const float4*)(w3 + k4));
                acc[3][0]+=wa.x*e0v.x+wa.y*e1v.x+wa.z*e2v.x+wa.w*e3v.x;
                acc[3][1]+=wa.x*e0v.y+wa.y*e1v.y+wa.z*e2v.y+wa.w*e3v.y;
                acc[3][2]+=wa.x*e0v.z+wa.y*e1v.z+wa.z*e2v.z+wa.w*e3v.z;
                acc[3][3]+=wa.x*e0v.w+wa.y*e1v.w+wa.z*e2v.w+wa.w*e3v.w;
            }
        }
        #pragma unroll
        for (int i = 0; i < 4; i++)
            *(float4*)&s_cor[(c0+i)*PD + d0] = make_float4(acc[i][0],acc[i][1],acc[i][2],acc[i][3]);
    }
    __syncthreads();

    // ---- stage 2: A[d][e] = sum_c corr[c][d]*q[c][e] (split-K x2 -> a0/a1) ----
    if (tid < 338) {
        const int t  = tid % 169;
        const int kh = tid / 169;
        const int d0 = (t / 13) * 4;
        const int e0 = (t % 13) * 4;
        const int k0 = kh * 64;
        float acc[4][4] = {};
        #pragma unroll 4
        for (int c = k0; c < k0 + 64; c++) {
            float4 cd = *(const float4*)&s_cor[c*PD + d0];
            float4 qe = *(const float4*)&s_q  [c*PD + e0];
            acc[0][0]+=cd.x*qe.x; acc[0][1]+=cd.x*qe.y; acc[0][2]+=cd.x*qe.z; acc[0][3]+=cd.x*qe.w;
            acc[1][0]+=cd.y*qe.x; acc[1][1]+=cd.y*qe.y; acc[1][2]+=cd.y*qe.z; acc[1][3]+=cd.y*qe.w;
            acc[2][0]+=cd.z*qe.x; acc[2][1]+=cd.z*qe.y; acc[2][2]+=cd.z*qe.z; acc[2][3]+=cd.z*qe.w;
            acc[3][0]+=cd.w*qe.x; acc[3][1]+=cd.w*qe.y; acc[3][2]+=cd.w*qe.z; acc[3][3]+=cd.w*qe.w;
        }
        float* dst = kh ? s_a1 : s_a0;
        #pragma unroll
        for (int i = 0; i < 4; i++)
            *(float4*)&dst[(d0+i)*PD + e0] = make_float4(acc[i][0],acc[i][1],acc[i][2],acc[i][3]);
    }
    __syncthreads();

    // ---- softmax pass 1: row/col max + sum stats (A = a0 + a1) ----
    for (int task = wid; task < 98; task += 16) {
        if (task < 49) {
            int e = task;
            float v0 = s_a0[lane*PD + e] + s_a1[lane*PD + e];
            float v1 = (lane < 17) ? s_a0[(lane+32)*PD + e] + s_a1[(lane+32)*PD + e] : -1e30f;
            float m = fmaxf(v0, v1);
            #pragma unroll
            for (int o = 16; o; o >>= 1) m = fmaxf(m, __shfl_xor_sync(~0u, m, o));
            float s = __expf(v0 - m) + ((lane < 17) ? __expf(v1 - m) : 0.f);
            #pragma unroll
            for (int o = 16; o; o >>= 1) s += __shfl_xor_sync(~0u, s, o);
            if (lane == 0) { s_cmax[e] = m; s_crs[e] = 1.f / s; }
        } else {
            int d = task - 49;
            float v0 = s_a0[d*PD + lane] + s_a1[d*PD + lane];
            float v1 = (lane < 17) ? s_a0[d*PD + lane+32] + s_a1[d*PD + lane+32] : -1e30f;
            float m = fmaxf(v0, v1);
            #pragma unroll
            for (int o = 16; o; o >>= 1) m = fmaxf(m, __shfl_xor_sync(~0u, m, o));
            float s = __expf(v0 - m) + ((lane < 17) ? __expf(v1 - m) : 0.f);
            #pragma unroll
            for (int o = 16; o; o >>= 1) s += __shfl_xor_sync(~0u, s, o);
            if (lane == 0) { s_rmax[d] = m; s_rrs[d] = 1.f / s; }
        }
    }
    __syncthreads();

    // ---- softmax pass 2: element-wise, in place (race-free) ----
    for (int t = tid; t < DD*DD; t += 512) {
        int d = t / DD, e = t % DD;
        int off = d*PD + e;
        float a = s_a0[off] + s_a1[off];
        s_a1[off] = __expf(a - s_cmax[e]) * s_crs[e];   // A1 (col softmax)
        s_a0[off] = __expf(a - s_rmax[d]) * s_rrs[d];   // B2 (row softmax)
    }
    __syncthreads();

    // ---- stage 3a: query_att[c][e] = sum_d ex[c][d]*A1[d][e]  (into s_cor) ----
    if (tid < 416) {
        const int c0 = (tid / 13) * 4;
        const int e0 = (tid % 13) * 4;
        float acc[4][4] = {};
        #pragma unroll 7
        for (int d = 0; d < DD; d++) {
            float4 av = *(const float4*)&s_a1[d*PD + e0];
            float x0 = s_ex[(c0+0)*PD + d];
            float x1 = s_ex[(c0+1)*PD + d];
            float x2 = s_ex[(c0+2)*PD + d];
            float x3 = s_ex[(c0+3)*PD + d];
            acc[0][0]+=x0*av.x; acc[0][1]+=x0*av.y; acc[0][2]+=x0*av.z; acc[0][3]+=x0*av.w;
            acc[1][0]+=x1*av.x; acc[1][1]+=x1*av.y; acc[1][2]+=x1*av.z; acc[1][3]+=x1*av.w;
            acc[2][0]+=x2*av.x; acc[2][1]+=x2*av.y; acc[2][2]+=x2*av.z; acc[2][3]+=x2*av.w;
            acc[3][0]+=x3*av.x; acc[3][1]+=x3*av.y; acc[3][2]+=x3*av.z; acc[3][3]+=x3*av.w;
        }
        #pragma unroll
        for (int i = 0; i < 4; i++)
            *(float4*)&s_cor[(c0+i)*PD + e0] = make_float4(acc[i][0],acc[i][1],acc[i][2],acc[i][3]);
    }
    __syncthreads();

    // ---- stage 3b: exemplar_att[c][d] = sum_e q[c][e]*B2[d][e]  (into s_ex) ----
    if (tid < 416) {
        const int c0 = (tid / 13) * 4;
        const int d0 = (tid % 13) * 4;
        float acc[4][4] = {};
        #pragma unroll 7
        for (int e = 0; e < DD; e++) {
            float b0 = s_a0[(d0+0)*PD + e];
            float b1 = s_a0[(d0+1)*PD + e];
            float b2 = s_a0[(d0+2)*PD + e];
            float b3 = s_a0[(d0+3)*PD + e];
            float x0 = s_q[(c0+0)*PD + e];
            float x1 = s_q[(c0+1)*PD + e];
            float x2 = s_q[(c0+2)*PD + e];
            float x3 = s_q[(c0+3)*PD + e];
            acc[0][0]+=x0*b0; acc[0][1]+=x0*b1; acc[0][2]+=x0*b2; acc[0][3]+=x0*b3;
            acc[1][0]+=x1*b0; acc[1][1]+=x1*b1; acc[1][2]+=x1*b2; acc[1][3]+=x1*b3;
            acc[2][0]+=x2*b0; acc[2][1]+=x2*b1; acc[2][2]+=x2*b2; acc[2][3]+=x2*b3;
            acc[3][0]+=x3*b0; acc[3][1]+=x3*b1; acc[3][2]+=x3*b2; acc[3][3]+=x3*b3;
        }
        #pragma unroll
        for (int i = 0; i < 4; i++)
            *(float4*)&s_ex[(c0+i)*PD + d0] = make_float4(acc[i][0],acc[i][1],acc[i][2],acc[i][3]);
    }
    __syncthreads();

    // ---- gates: warp per output pixel ----
    for (int task = wid; task < 98; task += 16) {
        if (task < 49) {
            int d = task; float s = 0.f;
            #pragma unroll
            for (int j = 0; j < 4; j++) { int c = lane + 32*j; s += s_g1[c] * s_ex[c*PD + d]; }
            #pragma unroll
            for (int o = 16; o; o >>= 1) s += __shfl_xor_sync(~0u, s, o);
            if (lane == 0) s_me[d] = 1.f / (1.f + __expf(-s));
        } else {
            int e = task - 49; float s = 0.f;
            #pragma unroll
            for (int j = 0; j < 4; j++) { int c = lane + 32*j; s += s_g2[c] * s_cor[c*PD + e]; }
            #pragma unroll
            for (int o = 16; o; o >>= 1) s += __shfl_xor_sync(~0u, s, o);
            if (lane == 0) s_mq[e] = 1.f / (1.f + __expf(-s));
        }
    }
    __syncthreads();

    // ---- recon + residual, direct scatter ----
    for (int i = tid; i < C1*DD; i += 512) {
        int c = i / DD, d = i % DD;
        int kh = d / KK, kw = d % KK;
        int y = phv*KK + kh, x = pwv*KK + kw;
        if (y < HH && x < WW) {
            size_t gi = (size_t)(n*C1 + c)*HW + y*WW + x;
            g_exsum[gi] = s_ex [c*PD + d]*s_me[d] + ex[gi];
            g_qsum [gi] = s_cor[c*PD + d]*s_mq[d] + q [gi];
        }
    }
}

// =====================================================================
// Depthwise 3x3 (pad 1) + BN + ReLU
// =====================================================================
__global__ __launch_bounds__(256) void dw_kernel(
    const float* __restrict__ in, float* __restrict__ out,
    const float* __restrict__ w, const float* __restrict__ g,
    const float* __restrict__ b, int Ctot, int total)
{
    int idx = blockIdx.x*blockDim.x + threadIdx.x;
    if (idx >= total) return;
    int x = idx % WW;
    int y = (idx / WW) % HH;
    int c = (idx / HW) % Ctot;
    const float* ip = in + (size_t)(idx - (y*WW + x));
    const float* wc = w + c*9;
    float acc = 0.f;
    #pragma unroll
    for (int dy = -1; dy <= 1; dy++) {
        int yy = y + dy;
        if (yy < 0 || yy >= HH) continue;
        #pragma unroll
        for (int dx = -1; dx <= 1; dx++) {
            int xx = x + dx;
            if (xx < 0 || xx >= WW) continue;
            acc += wc[(dy+1)*3 + (dx+1)] * ip[yy*WW + xx];
        }
    }
    float gs = g[c] * rsqrtf(1.f + 1e-5f);
    float v = acc*gs + b[c];
    out[idx] = v > 0.f ? v : 0.f;
}

// =====================================================================
// Pointwise 1x1 conv as SGEMM: 128co x 128px tile, 8x8 micro,
// double-buffered smem + register prefetch (1 barrier per k-chunk).
// =====================================================================
template<int CIN>
__global__ __launch_bounds__(256) void pw_kernel(
    const float* __restrict__ in, float* __restrict__ out,
    const float* __restrict__ w, const float* __restrict__ gsc,
    const float* __restrict__ bsc, int ostride, int co_off)
{
    __shared__ float As[2][8][128];
    __shared__ float Bs[2][8][128];
    const int n   = blockIdx.z;
    const int px0 = blockIdx.x * 128;
    const int t   = threadIdx.x;
    const int tx  = t % 16, ty = t / 16;
    const int ci  = t % 128, k4 = (t / 128) * 4;
    const int kr  = t / 32,  pc = (t % 32) * 4;

    float acc[8][8] = {};
    const float* inb = in + (size_t)n*CIN*HW + px0;

    float4 wv = __ldg((const float4*)(w + (size_t)ci*CIN + k4));
    float4 bv = __ldg((const float4*)(inb + (size_t)kr*HW + pc));

    for (int kt = 0; kt < CIN; kt += 8) {
        int buf = (kt >> 3) & 1;
        As[buf][k4+0][ci] = wv.x; As[buf][k4+1][ci] = wv.y;
        As[buf][k4+2][ci] = wv.z; As[buf][k4+3][ci] = wv.w;
        *(float4*)&Bs[buf][kr][pc] = bv;
        __syncthreads();
        if (kt + 8 < CIN) {
            wv = __ldg((const float4*)(w + (size_t)ci*CIN + kt + 8 + k4));
            bv = __ldg((const float4*)(inb + (size_t)(kt + 8 + kr)*HW + pc));
        }
        #pragma unroll
        for (int k = 0; k < 8; k++) {
            float4 a0 = *(float4*)&As[buf][k][ty*4];
            float4 a1 = *(float4*)&As[buf][k][64 + ty*4];
            float4 b0 = *(float4*)&Bs[buf][k][tx*4];
            float4 b1 = *(float4*)&Bs[buf][k][64 + tx*4];
            acc[0][0]+=a0.x*b0.x; acc[0][1]+=a0.x*b0.y; acc[0][2]+=a0.x*b0.z; acc[0][3]+=a0.x*b0.w;
            acc[0][4]+=a0.x*b1.x; acc[0][5]+=a0.x*b1.y; acc[0][6]+=a0.x*b1.z; acc[0][7]+=a0.x*b1.w;
            acc[1][0]+=a0.y*b0.x; acc[1][1]+=a0.y*b0.y; acc[1][2]+=a0.y*b0.z; acc[1][3]+=a0.y*b0.w;
            acc[1][4]+=a0.y*b1.x; acc[1][5]+=a0.y*b1.y; acc[1][6]+=a0.y*b1.z; acc[1][7]+=a0.y*b1.w;
            acc[2][0]+=a0.z*b0.x; acc[2][1]+=a0.z*b0.y; acc[2][2]+=a0.z*b0.z; acc[2][3]+=a0.z*b0.w;
            acc[2][4]+=a0.z*b1.x; acc[2][5]+=a0.z*b1.y; acc[2][6]+=a0.z*b1.z; acc[2][7]+=a0.z*b1.w;
            acc[3][0]+=a0.w*b0.x; acc[3][1]+=a0.w*b0.y; acc[3][2]+=a0.w*b0.z; acc[3][3]+=a0.w*b0.w;
            acc[3][4]+=a0.w*b1.x; acc[3][5]+=a0.w*b1.y; acc[3][6]+=a0.w*b1.z; acc[3][7]+=a0.w*b1.w;
            acc[4][0]+=a1.x*b0.x; acc[4][1]+=a1.x*b0.y; acc[4][2]+=a1.x*b0.z; acc[4][3]+=a1.x*b0.w;
            acc[4][4]+=a1.x*b1.x; acc[4][5]+=a1.x*b1.y; acc[4][6]+=a1.x*b1.z; acc[4][7]+=a1.x*b1.w;
            acc[5][0]+=a1.y*b0.x; acc[5][1]+=a1.y*b0.y; acc[5][2]+=a1.y*b0.z; acc[5][3]+=a1.y*b0.w;
            acc[5][4]+=a1.y*b1.x; acc[5][5]+=a1.y*b1.y; acc[5][6]+=a1.y*b1.z; acc[5][7]+=a1.y*b1.w;
            acc[6][0]+=a1.z*b0.x; acc[6][1]+=a1.z*b0.y; acc[6][2]+=a1.z*b0.z; acc[6][3]+=a1.z*b0.w;
            acc[6][4]+=a1.z*b1.x; acc[6][5]+=a1.z*b1.y; acc[6][6]+=a1.z*b1.z; acc[6][7]+=a1.z*b1.w;
            acc[7][0]+=a1.w*b0.x; acc[7][1]+=a1.w*b0.y; acc[7][2]+=a1.w*b0.z; acc[7][3]+=a1.w*b0.w;
            acc[7][4]+=a1.w*b1.x; acc[7][5]+=a1.w*b1.y; acc[7][6]+=a1.w*b1.z; acc[7][7]+=a1.w*b1.w;
        }
        __syncthreads();
    }

    #pragma unroll
    for (int i = 0; i < 8; i++) {
        int co = (i < 4) ? (ty*4 + i) : (64 + ty*4 + (i - 4));
        float gv = gsc[co] * rsqrtf(1.f + 1e-5f);
        float bb = bsc[co];
        float* ob = out + ((size_t)n*ostride + co_off + co)*HW + px0;
        float4 o0, o1;
        o0.x = fmaxf(acc[i][0]*gv + bb, 0.f);
        o0.y = fmaxf(acc[i][1]*gv + bb, 0.f);
        o0.z = fmaxf(acc[i][2]*gv + bb, 0.f);
        o0.w = fmaxf(acc[i][3]*gv + bb, 0.f);
        o1.x = fmaxf(acc[i][4]*gv + bb, 0.f);
        o1.y = fmaxf(acc[i][5]*gv + bb, 0.f);
        o1.z = fmaxf(acc[i][6]*gv + bb, 0.f);
        o1.w = fmaxf(acc[i][7]*gv + bb, 0.f);
        *(float4*)(ob + tx*4)      = o0;
        *(float4*)(ob + 64 + tx*4) = o1;
    }
}

// =====================================================================
extern "C" void kernel_launch(void* const* d_in, const int* in_sizes, int n_in,
                              void* d_out, int out_size)
{
    const float* exemplar = (const float*)d_in[0];
    const float* query    = (const float*)d_in[1];
    const float* w_conv_e = (const float*)d_in[2];
    const float* w_gate1  = (const float*)d_in[3];
    const float* w_gate2  = (const float*)d_in[4];
    const float* dw1_w    = (const float*)d_in[5];
    const float* bn1a_g   = (const float*)d_in[6];
    const float* bn1a_b   = (const float*)d_in[7];
    const float* pw1_w    = (const float*)d_in[8];
    const float* bn1b_g   = (const float*)d_in[9];
    const float* bn1b_b   = (const float*)d_in[10];
    const float* dwf_w    = (const float*)d_in[11];
    const float* bnfa_g   = (const float*)d_in[12];
    const float* bnfa_b   = (const float*)d_in[13];
    const float* pwf_w    = (const float*)d_in[14];
    const float* bnfb_g   = (const float*)d_in[15];
    const float* bnfb_b   = (const float*)d_in[16];

    float *p_exsum, *p_qsum, *p_dwex, *p_dwq, *p_cat, *p_dwf;
    cudaGetSymbolAddress((void**)&p_exsum, g_exsum);
    cudaGetSymbolAddress((void**)&p_qsum,  g_qsum);
    cudaGetSymbolAddress((void**)&p_dwex,  g_dwex);
    cudaGetSymbolAddress((void**)&p_dwq,   g_dwq);
    cudaGetSymbolAddress((void**)&p_cat,   g_cat);
    cudaGetSymbolAddress((void**)&p_dwf,   g_dwf);

    cudaFuncSetAttribute(attn_kernel, cudaFuncAttributeMaxDynamicSharedMemorySize, SMEM_BYTES);

    attn_kernel<<<NB*NPATCH, 512, SMEM_BYTES>>>(exemplar, query, w_conv_e, w_gate1, w_gate2);

    int tot1 = NB*C1*HW;
    dw_kernel<<<tot1/256, 256>>>(p_exsum, p_dwex, dw1_w, bn1a_g, bn1a_b, C1, tot1);
    dw_kernel<<<tot1/256, 256>>>(p_qsum,  p_dwq,  dw1_w, bn1a_g, bn1a_b, C1, tot1);
    pw_kernel<C1><<<dim3(HW/128, 1, NB), 256>>>(p_dwex, p_cat, pw1_w, bn1b_g, bn1b_b, 2*C1, 0);
    pw_kernel<C1><<<dim3(HW/128, 1, NB), 256>>>(p_dwq,  p_cat, pw1_w, bn1b_g, bn1b_b, 2*C1, C1);

    int tot2 = NB*2*C1*HW;
    dw_kernel<<<tot2/256, 256>>>(p_cat, p_dwf, dwf_w, bnfa_g, bnfa_b, 2*C1, tot2);
    pw_kernel<2*C1><<<dim3(HW/128, 1, NB), 256>>>(p_dwf, (float*)d_out, pwf_w, bnfb_g, bnfb_b, C1, 0);
}